// round 1
// baseline (speedup 1.0000x reference)
#include <cuda_runtime.h>

// NaiveTemporalShift: x[B,T,N,C] fp32, U=1 -> 3 channel partitions with
// temporal shifts [-1, 0, +1] at channel boundaries [0,86,171,256).
// out[b,t,n,c] = x[b, t - s(c), n, c] if in-bounds else 0.
//
// Pure memcpy-class kernel: ~352 MB total traffic -> target ~50-70 us.
// Strategy: one thread per output float4 (LDG.128/STG.128), scalar fixup
// only for the two misaligned boundary chunks per 64-chunk row.

#define TS_B 64
#define TS_T 128
#define TS_N 21
#define TS_C 256
#define TS_NC   (TS_N * TS_C)      // 5376 floats per (b,t) slice
#define TS_NC4  (TS_NC / 4)        // 1344 float4 per (b,t) slice
#define TS_TOTAL4 (TS_B * TS_T * TS_N * TS_C / 4)  // 11,010,048 float4

__global__ void __launch_bounds__(256)
temporal_shift_kernel(const float* __restrict__ xf, float* __restrict__ outf) {
    int idx = blockIdx.x * 256 + threadIdx.x;
    if (idx >= TS_TOTAL4) return;

    const float4* __restrict__ x4 = reinterpret_cast<const float4*>(xf);
    float4* __restrict__ o4 = reinterpret_cast<float4*>(outf);

    unsigned row = (unsigned)idx >> 6;        // (b*T + t)*N + n
    int c4 = idx & 63;                        // which float4 within C=256
    // row / N == b*T + t exactly (n < N); T = 128 -> mask gives t
    int t = (int)((row / TS_N) & (TS_T - 1));

    float4 r;
    if (c4 < 21) {
        // channels 0..83: shift -1 -> read t+1
        r = (t < TS_T - 1) ? x4[idx + TS_NC4] : make_float4(0.f, 0.f, 0.f, 0.f);
    } else if (c4 == 21) {
        // channels 84,85: shift -1 ; channels 86,87: shift 0
        float a0 = 0.f, a1 = 0.f;
        if (t < TS_T - 1) {
            a0 = xf[(idx + TS_NC4) * 4 + 0];
            a1 = xf[(idx + TS_NC4) * 4 + 1];
        }
        r.x = a0;
        r.y = a1;
        r.z = xf[idx * 4 + 2];
        r.w = xf[idx * 4 + 3];
    } else if (c4 < 42) {
        // channels 88..167: shift 0 -> straight copy
        r = x4[idx];
    } else if (c4 == 42) {
        // channels 168,169,170: shift 0 ; channel 171: shift +1
        r.x = xf[idx * 4 + 0];
        r.y = xf[idx * 4 + 1];
        r.z = xf[idx * 4 + 2];
        r.w = (t > 0) ? xf[(idx - TS_NC4) * 4 + 3] : 0.f;
    } else {
        // channels 172..255: shift +1 -> read t-1
        r = (t > 0) ? x4[idx - TS_NC4] : make_float4(0.f, 0.f, 0.f, 0.f);
    }

    o4[idx] = r;
}

extern "C" void kernel_launch(void* const* d_in, const int* in_sizes, int n_in,
                              void* d_out, int out_size) {
    const float* x = (const float*)d_in[0];
    float* out = (float*)d_out;
    int blocks = TS_TOTAL4 / 256;   // 43008, exact (TOTAL4 % 256 == 0)
    temporal_shift_kernel<<<blocks, 256>>>(x, out);
}

// round 2
// speedup vs baseline: 1.0582x; 1.0582x over previous
#include <cuda_runtime.h>

// NaiveTemporalShift: x[B,T,N,C] fp32, U=1 -> 3 channel partitions with
// temporal shifts [-1, 0, +1] at channel boundaries [0,86,171,256).
// out[b,t,n,c] = x[b, t - s(c), n, c] if in-bounds else 0.
//
// R1: 4 float4 per thread, split along B (stride TOTAL4/4) so all four share
// the same t and c4 -> branch + index math once, MLP_p1 = 4 independent
// LDG.128 in flight per thread. Streaming cache hints (no reuse).

#define TS_B 64
#define TS_T 128
#define TS_N 21
#define TS_C 256
#define TS_NC   (TS_N * TS_C)      // 5376 floats per (b,t) slice
#define TS_NC4  (TS_NC / 4)        // 1344 float4 per (b,t) slice
#define TS_TOTAL4 (TS_B * TS_T * TS_N * TS_C / 4)  // 11,010,048 float4
#define TS_Q (TS_TOTAL4 / 4)       // 2,752,512 (16 b's worth of float4)

__global__ void __launch_bounds__(256)
temporal_shift_kernel(const float* __restrict__ xf, float* __restrict__ outf) {
    int idx = blockIdx.x * 256 + threadIdx.x;   // in [0, TS_Q)

    const float4* __restrict__ x4 = reinterpret_cast<const float4*>(xf);
    float4* __restrict__ o4 = reinterpret_cast<float4*>(outf);

    unsigned row = (unsigned)idx >> 6;        // (b*T + t)*N + n, b in [0,16)
    int c4 = idx & 63;                        // which float4 within C=256
    int t = (int)((row / TS_N) & (TS_T - 1)); // same t for all 4 replicas

    const float4 zv = make_float4(0.f, 0.f, 0.f, 0.f);
    float4 r[4];

    if (c4 == 21) {
        // channels 84,85: shift -1 ; channels 86,87: shift 0
        bool ok = (t < TS_T - 1);
        #pragma unroll
        for (int k = 0; k < 4; k++) {
            int i = idx + k * TS_Q;
            r[k].x = ok ? __ldcs(xf + (i + TS_NC4) * 4 + 0) : 0.f;
            r[k].y = ok ? __ldcs(xf + (i + TS_NC4) * 4 + 1) : 0.f;
            r[k].z = __ldcs(xf + i * 4 + 2);
            r[k].w = __ldcs(xf + i * 4 + 3);
        }
    } else if (c4 == 42) {
        // channels 168,169,170: shift 0 ; channel 171: shift +1
        bool ok = (t > 0);
        #pragma unroll
        for (int k = 0; k < 4; k++) {
            int i = idx + k * TS_Q;
            r[k].x = __ldcs(xf + i * 4 + 0);
            r[k].y = __ldcs(xf + i * 4 + 1);
            r[k].z = __ldcs(xf + i * 4 + 2);
            r[k].w = ok ? __ldcs(xf + (i - TS_NC4) * 4 + 3) : 0.f;
        }
    } else {
        // uniform chunk: one shift for all 4 channels
        int del;
        bool zero;
        if (c4 < 21)      { del =  TS_NC4; zero = (t == TS_T - 1); }  // shift -1
        else if (c4 < 42) { del =  0;      zero = false;          }   // copy
        else              { del = -TS_NC4; zero = (t == 0);       }   // shift +1

        if (zero) {
            #pragma unroll
            for (int k = 0; k < 4; k++) r[k] = zv;
        } else {
            #pragma unroll
            for (int k = 0; k < 4; k++)
                r[k] = __ldcs(x4 + idx + k * TS_Q + del);
        }
    }

    #pragma unroll
    for (int k = 0; k < 4; k++)
        __stcs(o4 + idx + k * TS_Q, r[k]);
}

extern "C" void kernel_launch(void* const* d_in, const int* in_sizes, int n_in,
                              void* d_out, int out_size) {
    const float* x = (const float*)d_in[0];
    float* out = (float*)d_out;
    int blocks = TS_Q / 256;   // 10752, exact
    temporal_shift_kernel<<<blocks, 256>>>(x, out);
}